// round 11
// baseline (speedup 1.0000x reference)
#include <cuda_runtime.h>
#include <cuda_fp16.h>
#include <cstdint>

// ---------------------------------------------------------------------------
// EdgeClassNet, fully fp16-HMMA. R11: per-node precompute of layer-0 partials
// (u = h@W0[0:128], v = h@W0[128:256] -> g_uv), edge layer-0 reduced to
// gather-sum + one eattr k16 MMA step. 129 k16-steps/CTA (was 145).
// ---------------------------------------------------------------------------

constexpr int DN   = 256;   // node input dim
constexpr int IN   = 128;   // node hidden dim
constexpr int EA   = 16;
constexpr int NOUT = 3;

constexpr int MAXN = 65536;
constexpr int MAXE = 262144;

// 65 weight chunks: chunk 0 = W0e (eattr rows, K=16), chunks 1..64 = 8 mid
// layers x 8. Each chunk image: [256 n][40 k] fp16 = 20480 B. Paired fetches.
constexpr int NCHUNK = 65;
constexpr int WCH    = 20480;

__device__ __half g_hn[MAXN * IN];                 // 16 MB node hidden (fp16)
__device__ __half g_uv[MAXN * 512];                // 67 MB u|v partials (fp16)
__device__ int    g_ei[2 * MAXE];
__device__ __align__(16) unsigned char g_wpack[NCHUNK * WCH];
__device__ __align__(16) __half g_wxpack[128 * 264];   // node W: [n][k pad]
__device__ __align__(16) __half g_w0p[512 * 136];      // W0' : [512 n][136 k pad]

// ======================= merged prep kernel ================================
constexpr int NPACK_BLK = (NCHUNK * 256 * 40) / 256;   // 2600
constexpr int NWX_BLK   = (128 * 264) / 256;           // 132
constexpr int NW0P_BLK  = (512 * 136) / 256;           // 272

__global__ void prep_all(const int* __restrict__ ei_raw,
                         const float* __restrict__ W0,
                         const float* __restrict__ Wmid,
                         const float* __restrict__ Wx, int n2e)
{
    const int nconv = (n2e + 255) >> 8;
    const int b = blockIdx.x;
    if (b < nconv) {
        // dtype-detect (first 256 odd words, cached) + convert
        int nz = __syncthreads_or(ei_raw[2 * threadIdx.x + 1] != 0);
        int i = b * 256 + threadIdx.x;
        if (i < n2e) g_ei[i] = nz ? ei_raw[i] : ei_raw[2 * i];
    } else if (b < nconv + NPACK_BLK) {
        int idx = (b - nconv) * 256 + threadIdx.x;     // over 65*256*40
        int klocal = idx % 40;
        int n  = (idx / 40) & 255;
        int ch = idx / (40 * 256);
        float w = 0.f;
        if (ch == 0) {
            if (klocal < 16) w = W0[(256 + klocal) * 256 + n];
        } else {
            int L = (ch - 1) >> 3, cc = (ch - 1) & 7;
            int k = cc * 32 + klocal;
            if (klocal < 32) w = Wmid[L * 65536 + k * 256 + n];
        }
        *(__half*)(g_wpack + (size_t)ch * WCH + n * 80 + klocal * 2) = __float2half_rn(w);
    } else if (b < nconv + NPACK_BLK + NWX_BLK) {
        int idx = (b - nconv - NPACK_BLK) * 256 + threadIdx.x;  // over 128*264
        int n = idx / 264, k = idx % 264;
        g_wxpack[idx] = __float2half_rn(k < 256 ? Wx[k * 128 + n] : 0.f);
    } else {
        int idx = (b - nconv - NPACK_BLK - NWX_BLK) * 256 + threadIdx.x;  // 512*136
        int m = idx / 136, k = idx % 136;
        float w = 0.f;
        if (k < 128)
            w = (m < 256) ? W0[k * 256 + m] : W0[(128 + k) * 256 + (m - 256)];
        g_w0p[idx] = __float2half_rn(w);
    }
}

// ======================= PTX helpers =======================================
__device__ __forceinline__ uint32_t smem_u32(const void* p) {
    uint32_t a;
    asm("{ .reg .u64 t; cvta.to.shared.u64 t, %1; cvt.u32.u64 %0, t; }"
        : "=r"(a) : "l"(p));
    return a;
}
__device__ __forceinline__ void cp16b(char* dst, const char* src) {
    unsigned u = (unsigned)__cvta_generic_to_shared(dst);
    asm volatile("cp.async.cg.shared.global [%0], [%1], 16;" :: "r"(u), "l"(src));
}
__device__ __forceinline__ void cp_commit() { asm volatile("cp.async.commit_group;"); }
template<int N> __device__ __forceinline__ void cp_wait() {
    asm volatile("cp.async.wait_group %0;" :: "n"(N));
}
__device__ __forceinline__ void mbar_init(uint32_t a, uint32_t cnt) {
    asm volatile("mbarrier.init.shared.b64 [%0], %1;" :: "r"(a), "r"(cnt) : "memory");
}
__device__ __forceinline__ void mbar_expect_tx(uint32_t a, uint32_t bytes) {
    asm volatile("mbarrier.arrive.expect_tx.shared.b64 _, [%0], %1;"
                 :: "r"(a), "r"(bytes) : "memory");
}
__device__ __forceinline__ void bulk_g2s(uint32_t dst, const void* src,
                                         uint32_t bytes, uint32_t mbar) {
    asm volatile(
        "cp.async.bulk.shared::cluster.global.mbarrier::complete_tx::bytes "
        "[%0], [%1], %2, [%3];"
        :: "r"(dst), "l"(src), "r"(bytes), "r"(mbar) : "memory");
}
__device__ __forceinline__ void mbar_wait(uint32_t mbar, uint32_t parity) {
    asm volatile(
        "{\n\t.reg .pred P1;\n\t"
        "WAIT_LOOP_%=:\n\t"
        "mbarrier.try_wait.parity.acquire.cta.shared::cta.b64 P1, [%0], %1, 0x989680;\n\t"
        "@P1 bra.uni WAIT_DONE_%=;\n\t"
        "bra.uni WAIT_LOOP_%=;\n\t"
        "WAIT_DONE_%=:\n\t}"
        :: "r"(mbar), "r"(parity) : "memory");
}
__device__ __forceinline__ void ldm_x4(uint32_t* r, uint32_t addr) {
    asm volatile("ldmatrix.sync.aligned.m8n8.x4.shared.b16 {%0,%1,%2,%3}, [%4];"
                 : "=r"(r[0]), "=r"(r[1]), "=r"(r[2]), "=r"(r[3]) : "r"(addr));
}
__device__ __forceinline__ void mma16816(float* c, const uint32_t* a,
                                         uint32_t b0, uint32_t b1) {
    asm volatile(
        "mma.sync.aligned.m16n8k16.row.col.f32.f16.f16.f32 "
        "{%0,%1,%2,%3}, {%4,%5,%6,%7}, {%8,%9}, {%0,%1,%2,%3};"
        : "+f"(c[0]), "+f"(c[1]), "+f"(c[2]), "+f"(c[3])
        : "r"(a[0]), "r"(a[1]), "r"(a[2]), "r"(a[3]), "r"(b0), "r"(b1));
}
__device__ __forceinline__ uint32_t h2(float v0, float v1) {
    __half2 h = __floats2half2_rn(v0, v1);
    return *(uint32_t*)&h;
}
__device__ __forceinline__ uint32_t hadd2u(uint32_t x, uint32_t y) {
    __half2 r = __hadd2(*(__half2*)&x, *(__half2*)&y);
    return *(uint32_t*)&r;
}
// full 64x64 MMA block: 32 HMMA
__device__ __forceinline__ void mma_block(float (*c)[8][4],
                                          const uint32_t (*a)[4],
                                          const uint32_t (*b)[4]) {
#pragma unroll
    for (int i = 0; i < 4; i++)
#pragma unroll
        for (int j = 0; j < 4; j++) {
            mma16816(c[i][2 * j],     a[i], b[j][0], b[j][1]);
            mma16816(c[i][2 * j + 1], a[i], b[j][2], b[j][3]);
        }
}

// ======================= node MLP on fp16 HMMA (unchanged) =================
constexpr int NA_STR  = 280;                     // halves
constexpr int NW_STR  = 264;                     // halves
constexpr int NOFF_W  = 64 * NA_STR * 2;         // 35840 B
constexpr int SMEM_N  = NOFF_W + 128 * NW_STR * 2;  // 103424 B

__global__ void __launch_bounds__(128, 2)
node_hmma_kernel(const float* __restrict__ x, const float* __restrict__ bx)
{
    extern __shared__ char smc[];
    const uint32_t sbase = smem_u32(smc);
    const int tid = threadIdx.x, wid = tid >> 5, lane = tid & 31;
    const long long r0 = (long long)blockIdx.x * 64;

    {
        const char* src = (const char*)g_wxpack;
        char* dst = smc + NOFF_W;
#pragma unroll
        for (int i = 0; i < 33; i++) {
            int idx = tid + i * 128;
            cp16b(dst + idx * 16, src + idx * 16);
        }
        cp_commit();
    }
    {
        const float4* x4 = (const float4*)(x + r0 * DN);
#pragma unroll
        for (int g = 0; g < 32; g++) {
            int f = tid + 128 * g;
            int row = f >> 6, col = f & 63;
            float4 v = x4[f];
            char* dst = smc + row * (NA_STR * 2) + col * 8;
            *(uint32_t*)(dst)     = h2(v.x, v.y);
            *(uint32_t*)(dst + 4) = h2(v.z, v.w);
        }
    }
    cp_wait<0>();
    __syncthreads();

    const int i7 = lane & 7;
    const int rowOff  = ((lane >> 3) & 1) * 8 + i7;
    const int aColOff = (lane >= 16) ? 16 : 0;
    const uint32_t aBase = sbase + (uint32_t)(16 * wid + rowOff) * (NA_STR * 2) + aColOff;
    const int nIdx  = ((lane >= 16) ? 8 : 0) + i7;
    const int bkOff = ((lane >> 3) & 1) * 16;
    uint32_t bB[8];
#pragma unroll
    for (int j = 0; j < 8; j++)
        bB[j] = sbase + NOFF_W + (uint32_t)(nIdx + 16 * j) * (NW_STR * 2) + bkOff;

    float c[16][4];
#pragma unroll
    for (int j = 0; j < 16; j++)
#pragma unroll
        for (int q = 0; q < 4; q++) c[j][q] = 0.f;

#pragma unroll 4
    for (int k = 0; k < 16; k++) {
        uint32_t a[4];
        ldm_x4(a, aBase + k * 32);
#pragma unroll
        for (int j = 0; j < 8; j++) {
            uint32_t b[4];
            ldm_x4(b, bB[j] + k * 32);
            mma16816(c[2 * j],     a, b[0], b[1]);
            mma16816(c[2 * j + 1], a, b[2], b[3]);
        }
    }

    const long long rb = r0 + 16 * wid + (lane >> 2);
#pragma unroll
    for (int j = 0; j < 16; j++) {
        int col = 8 * j + 2 * (lane & 3);
        float2 bb = __ldg((const float2*)(bx + col));
#pragma unroll
        for (int r8 = 0; r8 < 2; r8++) {
            float v0 = c[j][2 * r8]     + bb.x;
            float v1 = c[j][2 * r8 + 1] + bb.y;
            v0 = fmaxf(v0, 0.01f * v0);
            v1 = fmaxf(v1, 0.01f * v1);
            *(uint32_t*)((char*)g_hn + ((rb + 8 * r8) * IN + col) * 2) = h2(v0, v1);
        }
    }
}

// ======================= uv precompute: g_uv = g_hn @ W0' ==================
// 128 rows/CTA, [128 rows][512 cols], K=128. A [128][136]h, W [512][136]h.
constexpr int UA_STR  = 272;                     // bytes (136 halves)
constexpr int UOFF_W  = 128 * UA_STR;            // 34816
constexpr int SMEM_UV = UOFF_W + 512 * UA_STR;   // 174080

__global__ void __launch_bounds__(256, 1)
uv_kernel()
{
    extern __shared__ char smc[];
    const uint32_t sbase = smem_u32(smc);
    const int tid = threadIdx.x, wid = tid >> 5, lane = tid & 31;
    const int mg = wid >> 2, ng = wid & 3;
    const int RB = 64 * mg, CB = 128 * ng;
    const long long r0 = (long long)blockIdx.x * 128;

    // stage A (g_hn rows, straight copy with stride pad)
    {
        const char* src = (const char*)(g_hn + r0 * IN);
#pragma unroll
        for (int i = 0; i < 8; i++) {
            int idx = tid + i * 256;               // uint4 index over [128][16]
            int row = idx >> 4, col = idx & 15;
            cp16b(smc + row * UA_STR + col * 16, src + idx * 16);
        }
    }
    // stage W0' image (8704 uint4)
    {
        const char* src = (const char*)g_w0p;
        char* dst = smc + UOFF_W;
#pragma unroll
        for (int i = 0; i < 34; i++) {
            int idx = tid + i * 256;
            cp16b(dst + idx * 16, src + idx * 16);
        }
    }
    cp_commit();
    cp_wait<0>();
    __syncthreads();

    const int i7 = lane & 7;
    const int rowOff  = ((lane >> 3) & 1) * 8 + i7;
    const int aColOff = (lane >= 16) ? 16 : 0;
    uint32_t aB[4];
#pragma unroll
    for (int i = 0; i < 4; i++)
        aB[i] = sbase + (uint32_t)(RB + 16 * i + rowOff) * UA_STR + aColOff;
    const int nIdx  = ((lane >= 16) ? 8 : 0) + i7;
    const int bkOff = ((lane >> 3) & 1) * 16;
    uint32_t bB[4];
#pragma unroll
    for (int j = 0; j < 4; j++)
        bB[j] = sbase + UOFF_W + (uint32_t)(CB + nIdx + 16 * j) * UA_STR + bkOff;

    float c[4][8][4];
#pragma unroll
    for (int i = 0; i < 4; i++)
#pragma unroll
        for (int j = 0; j < 8; j++)
#pragma unroll
            for (int q = 0; q < 4; q++) c[i][j][q] = 0.f;

#pragma unroll 2
    for (int k = 0; k < 8; k++) {
        uint32_t a[4][4], b[4][4];
#pragma unroll
        for (int j = 0; j < 4; j++) ldm_x4(b[j], bB[j] + k * 32);
#pragma unroll
        for (int i = 0; i < 4; i++) ldm_x4(a[i], aB[i] + k * 32);
        mma_block(c, a, b);
    }

    // write raw fp16 partials
#pragma unroll
    for (int i = 0; i < 4; i++) {
        const long long rb = r0 + RB + 16 * i + (lane >> 2);
#pragma unroll
        for (int j = 0; j < 8; j++) {
            int col = CB + 8 * j + 2 * (lane & 3);
            *(uint32_t*)((char*)g_uv + ((rb)     * 512 + col) * 2) = h2(c[i][j][0], c[i][j][1]);
            *(uint32_t*)((char*)g_uv + ((rb + 8) * 512 + col) * 2) = h2(c[i][j][2], c[i][j][3]);
        }
    }
}

// ======================= edge MLP on fp16 mma.sync =========================
constexpr int ASTRB  = 528;                      // A row stride: 264 fp16
constexpr int OFF_S  = 128 * ASTRB;              // 67584: s buffer [128][264]h
constexpr int OFF_PT = OFF_S;                    // classifier partials (reuse)
constexpr int OFF_W  = OFF_S + 128 * ASTRB;      // 135168: 2 pair-slots x 40960
constexpr int OFF_MB = OFF_W + 2 * 2 * WCH;      // 217088 (2 mbarriers)
constexpr int SMEM_E = OFF_MB + 64;              // 217152

__device__ __forceinline__ uint32_t chunk_buf(uint32_t sbase, int c) {
    return sbase + OFF_W + (uint32_t)(((c >> 1) & 1) * (2 * WCH)) +
           (uint32_t)((c & 1) * WCH);
}
__device__ __forceinline__ void wait_pair(uint32_t sbase, int p) {
    mbar_wait(sbase + OFF_MB + (p & 1) * 8, (uint32_t)((p >> 1) & 1));
}
__device__ __forceinline__ void fetch_pair(uint32_t sbase, int p) {
    uint32_t mb = sbase + OFF_MB + (p & 1) * 8;
    uint32_t bytes = (2 * p + 1 < NCHUNK) ? 2 * WCH : WCH;
    mbar_expect_tx(mb, bytes);
    bulk_g2s(sbase + OFF_W + (p & 1) * (2 * WCH),
             g_wpack + (size_t)(2 * p) * WCH, bytes, mb);
}

__global__ void __launch_bounds__(256, 1)
edge_hmma_kernel(const float* __restrict__ eattr,
                 const float* __restrict__ b0, const float* __restrict__ bmid,
                 const float* __restrict__ Wlast, const float* __restrict__ blast,
                 float* __restrict__ out, int E)
{
    extern __shared__ char smc[];
    const uint32_t sbase = smem_u32(smc);
    const int tid = threadIdx.x, wid = tid >> 5, lane = tid & 31;
    const int mg = wid >> 2, ng = wid & 3;        // 2 x 4 warp grid
    const int RB = 64 * mg, CB = 64 * ng;
    const long long e0 = (long long)blockIdx.x * 128;

    if (tid == 0) {
        mbar_init(sbase + OFF_MB, 1);
        mbar_init(sbase + OFF_MB + 8, 1);
    }
    __syncthreads();
    if (tid == 0) { fetch_pair(sbase, 0); fetch_pair(sbase, 1); }

    // ---------------- gather: s = u[row] + v[col]; eattr -> A cols 0..15 ----
    {
        int e = tid >> 1, half = tid & 1;
        long long ge = e0 + e;
        const uint4* up = (const uint4*)(g_uv + (size_t)g_ei[ge] * 512 + half * 128);
        const uint4* vp = (const uint4*)(g_uv + (size_t)g_ei[(long long)E + ge] * 512
                                         + 256 + half * 128);
        uint4* dst = (uint4*)(smc + OFF_S + e * ASTRB + half * 256);
#pragma unroll
        for (int g = 0; g < 16; g++) {
            uint4 a = up[g], b = vp[g], r;
            r.x = hadd2u(a.x, b.x); r.y = hadd2u(a.y, b.y);
            r.z = hadd2u(a.z, b.z); r.w = hadd2u(a.w, b.w);
            dst[g] = r;
        }
        if (half == 0) {
            const float4* ea4 = (const float4*)(eattr + ge * EA);
            uint4* ad = (uint4*)(smc + e * ASTRB);
#pragma unroll
            for (int g = 0; g < 2; g++) {
                float4 f0 = ea4[2 * g], f1 = ea4[2 * g + 1];
                uint4 u;
                u.x = h2(f0.x, f0.y); u.y = h2(f0.z, f0.w);
                u.z = h2(f1.x, f1.y); u.w = h2(f1.z, f1.w);
                ad[g] = u;
            }
        }
    }
    __syncthreads();

    // ---------------- per-thread invariant addresses ------------------------
    const int i7 = lane & 7;
    const int rowOff  = ((lane >> 3) & 1) * 8 + i7;
    const int aColOff = (lane >= 16) ? 16 : 0;            // bytes
    uint32_t aB[4];
#pragma unroll
    for (int i = 0; i < 4; i++)
        aB[i] = sbase + (uint32_t)(RB + 16 * i + rowOff) * ASTRB + aColOff;
    const int nIdx  = CB + ((lane >= 16) ? 8 : 0) + i7;
    const int bkOff = ((lane >> 3) & 1) * 16;             // bytes
    uint32_t bB[4];
#pragma unroll
    for (int j = 0; j < 4; j++) bB[j] = (uint32_t)(nIdx + 16 * j) * 80 + bkOff;

    float c[4][8][4];
#pragma unroll
    for (int i = 0; i < 4; i++)
#pragma unroll
        for (int j = 0; j < 8; j++)
#pragma unroll
            for (int q = 0; q < 4; q++) c[i][j][q] = 0.f;

    uint32_t bf0[4][4], bf1[4][4];

    // ---------------- L0: single k16 step (eattr @ W0e) ---------------------
    wait_pair(sbase, 0);
    {
        uint32_t a0[4][4];
        const uint32_t buf0 = chunk_buf(sbase, 0);
#pragma unroll
        for (int j = 0; j < 4; j++) ldm_x4(bf0[j], buf0 + bB[j]);
#pragma unroll
        for (int i = 0; i < 4; i++) ldm_x4(a0[i], aB[i]);   // eattr cols 0-15
        mma_block(c, a0, bf0);
        const uint32_t buf1 = chunk_buf(sbase, 1);          // pair 0, present
#pragma unroll
        for (int j = 0; j < 4; j++) ldm_x4(bf0[j], buf1 + bB[j]);
    }
    __syncthreads();   // all eattr A-reads done before overwrite

    // L0 epilogue: C += s + b0, leaky -> A plane; zero C
    {
#pragma unroll
        for (int i = 0; i < 4; i++) {
            const int row0 = RB + 16 * i + (lane >> 2);
#pragma unroll
            for (int j = 0; j < 8; j++) {
                const int col = CB + 8 * j + 2 * (lane & 3);
                float2 bb = __ldg((const float2*)(b0 + col));
                uint32_t sw0 = *(uint32_t*)(smc + OFF_S + row0 * ASTRB + col * 2);
                uint32_t sw1 = *(uint32_t*)(smc + OFF_S + (row0 + 8) * ASTRB + col * 2);
                float2 s0 = __half22float2(*(__half2*)&sw0);
                float2 s1 = __half22float2(*(__half2*)&sw1);
                float v0 = c[i][j][0] + s0.x + bb.x, v1 = c[i][j][1] + s0.y + bb.y;
                float v2 = c[i][j][2] + s1.x + bb.x, v3 = c[i][j][3] + s1.y + bb.y;
                v0 = fmaxf(v0, 0.01f * v0); v1 = fmaxf(v1, 0.01f * v1);
                v2 = fmaxf(v2, 0.01f * v2); v3 = fmaxf(v3, 0.01f * v3);
                char* p0 = smc + row0 * ASTRB + col * 2;
                *(uint32_t*)(p0)             = h2(v0, v1);
                *(uint32_t*)(p0 + 8 * ASTRB) = h2(v2, v3);
                c[i][j][0] = 0.f; c[i][j][1] = 0.f;
                c[i][j][2] = 0.f; c[i][j][3] = 0.f;
            }
        }
    }
    __syncthreads();

    // ---------------- layers 1..8: 4 pair-iterations each -------------------
    int t = 0;   // iteration index 0..31; consumes chunks (2t+1, 2t+2)
#pragma unroll 1
    for (int L = 1; L <= 8; L++) {
#pragma unroll 1
        for (int p = 0; p < 4; p++) {
            const int ca = 2 * t + 1, cb = ca + 1, nc = cb + 1;
            const int kA = p * 128;
            const uint32_t bufA = chunk_buf(sbase, ca);
            uint32_t a[4][4];

#pragma unroll
            for (int j = 0; j < 4; j++) ldm_x4(bf1[j], bufA + bB[j] + 32);
#pragma unroll
            for (int i = 0; i < 4; i++) ldm_x4(a[i], aB[i] + kA);
            mma_block(c, a, bf0);
            wait_pair(sbase, t + 1);                       // pair of cb
            const uint32_t bufB = chunk_buf(sbase, cb);
#pragma unroll
            for (int i = 0; i < 4; i++) ldm_x4(a[i], aB[i] + kA + 32);
#pragma unroll
            for (int j = 0; j < 4; j++) ldm_x4(bf0[j], bufB + bB[j]);
            mma_block(c, a, bf1);
#pragma unroll
            for (int j = 0; j < 4; j++) ldm_x4(bf1[j], bufB + bB[j] + 32);
#pragma unroll
            for (int i = 0; i < 4; i++) ldm_x4(a[i], aB[i] + kA + 64);
            mma_block(c, a, bf0);
#pragma unroll
            for (int i = 0; i < 4; i++) ldm_x4(a[i], aB[i] + kA + 96);
            if (nc < NCHUNK) {
                const uint32_t bufN = chunk_buf(sbase, nc);  // pair t+1, present
#pragma unroll
                for (int j = 0; j < 4; j++) ldm_x4(bf0[j], bufN + bB[j]);
            }
            mma_block(c, a, bf1);

            __syncthreads();                // pair t fully consumed by all warps
            if (tid == 0 && t + 2 <= 32) fetch_pair(sbase, t + 2);
            t++;
        }

        if (L < 8) {
            // epilogue: leaky(D + bias) -> fp16 -> A plane; zero C
            const float* bias = bmid + (L - 1) * 256;
#pragma unroll
            for (int i = 0; i < 4; i++) {
                const int row0 = RB + 16 * i + (lane >> 2);
#pragma unroll
                for (int j = 0; j < 8; j++) {
                    const int col = CB + 8 * j + 2 * (lane & 3);
                    float2 bb = __ldg((const float2*)(bias + col));
                    float v0 = c[i][j][0] + bb.x, v1 = c[i][j][1] + bb.y;
                    float v2 = c[i][j][2] + bb.x, v3 = c[i][j][3] + bb.y;
                    v0 = fmaxf(v0, 0.01f * v0); v1 = fmaxf(v1, 0.01f * v1);
                    v2 = fmaxf(v2, 0.01f * v2); v3 = fmaxf(v3, 0.01f * v3);
                    char* p0 = smc + row0 * ASTRB + col * 2;
                    *(uint32_t*)(p0)             = h2(v0, v1);
                    *(uint32_t*)(p0 + 8 * ASTRB) = h2(v2, v3);
                    c[i][j][0] = 0.f; c[i][j][1] = 0.f;
                    c[i][j][2] = 0.f; c[i][j][3] = 0.f;
                }
            }
            __syncthreads();
        }
    }

    // ---------------- classifier + log_softmax ------------------------------
    {
        const float* bias = bmid + 7 * 256;
        float p[4][2][3];
#pragma unroll
        for (int i = 0; i < 4; i++)
#pragma unroll
            for (int h = 0; h < 2; h++)
                p[i][h][0] = p[i][h][1] = p[i][h][2] = 0.f;
#pragma unroll
        for (int i = 0; i < 4; i++) {
#pragma unroll
            for (int j = 0; j < 8; j++) {
                const int col = CB + 8 * j + 2 * (lane & 3);
                float2 bb = __ldg((const float2*)(bias + col));
                float v0 = c[i][j][0] + bb.x, v1 = c[i][j][1] + bb.y;
                float v2 = c[i][j][2] + bb.x, v3 = c[i][j][3] + bb.y;
                v0 = fmaxf(v0, 0.01f * v0); v1 = fmaxf(v1, 0.01f * v1);
                v2 = fmaxf(v2, 0.01f * v2); v3 = fmaxf(v3, 0.01f * v3);
                const float* w0 = Wlast + col * 3;
#pragma unroll
                for (int k = 0; k < 3; k++) {
                    float wa = __ldg(w0 + k), wb2 = __ldg(w0 + 3 + k);
                    p[i][0][k] = fmaf(v0, wa, fmaf(v1, wb2, p[i][0][k]));
                    p[i][1][k] = fmaf(v2, wa, fmaf(v3, wb2, p[i][1][k]));
                }
            }
        }
#pragma unroll
        for (int i = 0; i < 4; i++)
#pragma unroll
            for (int h = 0; h < 2; h++)
#pragma unroll
                for (int k = 0; k < 3; k++) {
                    float v = p[i][h][k];
                    v += __shfl_xor_sync(0xffffffffu, v, 1);
                    v += __shfl_xor_sync(0xffffffffu, v, 2);
                    p[i][h][k] = v;
                }
        float* pt = (float*)(smc + OFF_PT);   // [128 rows][4 ng][3]
        __syncthreads();                       // S region reads long done; reuse
        if ((lane & 3) == 0) {
#pragma unroll
            for (int i = 0; i < 4; i++)
#pragma unroll
                for (int h = 0; h < 2; h++) {
                    int row = RB + 16 * i + (lane >> 2) + 8 * h;
#pragma unroll
                    for (int k = 0; k < 3; k++)
                        pt[(row * 4 + ng) * 3 + k] = p[i][h][k];
                }
        }
    }
    __syncthreads();
    if (tid < 128) {
        const float* pt = (const float*)(smc + OFF_PT);
        float l[3];
#pragma unroll
        for (int k = 0; k < 3; k++) {
            float s = __ldg(blast + k);
#pragma unroll
            for (int g = 0; g < 4; g++) s += pt[(tid * 4 + g) * 3 + k];
            l[k] = s;
        }
        float mx  = fmaxf(l[0], fmaxf(l[1], l[2]));
        float lse = mx + logf(expf(l[0] - mx) + expf(l[1] - mx) + expf(l[2] - mx));
        float* o = out + (e0 + tid) * NOUT;
        o[0] = l[0] - lse; o[1] = l[1] - lse; o[2] = l[2] - lse;
    }
}

// ===========================================================================
extern "C" void kernel_launch(void* const* d_in, const int* in_sizes, int n_in,
                              void* d_out, int out_size)
{
    const float* x      = (const float*)d_in[0];
    const int*   ei_raw = (const int*)d_in[1];
    const float* eattr  = (const float*)d_in[2];
    const float* Wx     = (const float*)d_in[3];
    const float* bx     = (const float*)d_in[4];
    const float* W0     = (const float*)d_in[5];
    const float* b0     = (const float*)d_in[6];
    const float* Wmid   = (const float*)d_in[7];
    const float* bmid   = (const float*)d_in[8];
    const float* Wlast  = (const float*)d_in[9];
    const float* blast  = (const float*)d_in[10];
    float* out = (float*)d_out;

    const int N  = in_sizes[0] / DN;
    const int E  = in_sizes[2] / EA;
    const int n2 = 2 * E;
    const int nconv = (n2 + 255) / 256;

    cudaFuncSetAttribute(node_hmma_kernel,
                         cudaFuncAttributeMaxDynamicSharedMemorySize, SMEM_N);
    cudaFuncSetAttribute(uv_kernel,
                         cudaFuncAttributeMaxDynamicSharedMemorySize, SMEM_UV);
    cudaFuncSetAttribute(edge_hmma_kernel,
                         cudaFuncAttributeMaxDynamicSharedMemorySize, SMEM_E);

    prep_all<<<nconv + NPACK_BLK + NWX_BLK + NW0P_BLK, 256>>>(ei_raw, W0, Wmid, Wx, n2);
    node_hmma_kernel<<<N / 64, 128, SMEM_N>>>(x, bx);
    uv_kernel<<<N / 128, 256, SMEM_UV>>>();
    edge_hmma_kernel<<<E / 128, 256, SMEM_E>>>(eattr, b0, bmid, Wlast, blast,
                                               out, E);
}

// round 12
// speedup vs baseline: 1.1207x; 1.1207x over previous
#include <cuda_runtime.h>
#include <cuda_fp16.h>
#include <cstdint>

// ---------------------------------------------------------------------------
// EdgeClassNet, fully fp16-HMMA. R12: uv precompute retained; S buffer
// eliminated (L0 epilogue loads u/v straight from g_uv) -> 3 pair-slot
// weight ring restored (1.5-iteration fetch lead).
// ---------------------------------------------------------------------------

constexpr int DN   = 256;   // node input dim
constexpr int IN   = 128;   // node hidden dim
constexpr int EA   = 16;
constexpr int NOUT = 3;

constexpr int MAXN = 65536;
constexpr int MAXE = 262144;

// 65 weight chunks: chunk 0 = W0e (eattr rows, K=16), chunks 1..64 = 8 mid
// layers x 8. Each chunk image: [256 n][40 k] fp16 = 20480 B. Paired fetches.
constexpr int NCHUNK = 65;
constexpr int WCH    = 20480;

__device__ __half g_hn[MAXN * IN];                 // 16 MB node hidden (fp16)
__device__ __half g_uv[MAXN * 512];                // 67 MB u|v partials (fp16)
__device__ int    g_ei[2 * MAXE];
__device__ __align__(16) unsigned char g_wpack[NCHUNK * WCH];
__device__ __align__(16) __half g_wxpack[128 * 264];   // node W: [n][k pad]
__device__ __align__(16) __half g_w0p[512 * 136];      // W0' : [512 n][136 k pad]

// ======================= merged prep kernel ================================
constexpr int NPACK_BLK = (NCHUNK * 256 * 40) / 256;   // 2600
constexpr int NWX_BLK   = (128 * 264) / 256;           // 132
constexpr int NW0P_BLK  = (512 * 136) / 256;           // 272

__global__ void prep_all(const int* __restrict__ ei_raw,
                         const float* __restrict__ W0,
                         const float* __restrict__ Wmid,
                         const float* __restrict__ Wx, int n2e)
{
    const int nconv = (n2e + 255) >> 8;
    const int b = blockIdx.x;
    if (b < nconv) {
        int nz = __syncthreads_or(ei_raw[2 * threadIdx.x + 1] != 0);
        int i = b * 256 + threadIdx.x;
        if (i < n2e) g_ei[i] = nz ? ei_raw[i] : ei_raw[2 * i];
    } else if (b < nconv + NPACK_BLK) {
        int idx = (b - nconv) * 256 + threadIdx.x;     // over 65*256*40
        int klocal = idx % 40;
        int n  = (idx / 40) & 255;
        int ch = idx / (40 * 256);
        float w = 0.f;
        if (ch == 0) {
            if (klocal < 16) w = W0[(256 + klocal) * 256 + n];
        } else {
            int L = (ch - 1) >> 3, cc = (ch - 1) & 7;
            int k = cc * 32 + klocal;
            if (klocal < 32) w = Wmid[L * 65536 + k * 256 + n];
        }
        *(__half*)(g_wpack + (size_t)ch * WCH + n * 80 + klocal * 2) = __float2half_rn(w);
    } else if (b < nconv + NPACK_BLK + NWX_BLK) {
        int idx = (b - nconv - NPACK_BLK) * 256 + threadIdx.x;  // over 128*264
        int n = idx / 264, k = idx % 264;
        g_wxpack[idx] = __float2half_rn(k < 256 ? Wx[k * 128 + n] : 0.f);
    } else {
        int idx = (b - nconv - NPACK_BLK - NWX_BLK) * 256 + threadIdx.x;  // 512*136
        int m = idx / 136, k = idx % 136;
        float w = 0.f;
        if (k < 128)
            w = (m < 256) ? W0[k * 256 + m] : W0[(128 + k) * 256 + (m - 256)];
        g_w0p[idx] = __float2half_rn(w);
    }
}

// ======================= PTX helpers =======================================
__device__ __forceinline__ uint32_t smem_u32(const void* p) {
    uint32_t a;
    asm("{ .reg .u64 t; cvta.to.shared.u64 t, %1; cvt.u32.u64 %0, t; }"
        : "=r"(a) : "l"(p));
    return a;
}
__device__ __forceinline__ void cp16b(char* dst, const char* src) {
    unsigned u = (unsigned)__cvta_generic_to_shared(dst);
    asm volatile("cp.async.cg.shared.global [%0], [%1], 16;" :: "r"(u), "l"(src));
}
__device__ __forceinline__ void cp_commit() { asm volatile("cp.async.commit_group;"); }
template<int N> __device__ __forceinline__ void cp_wait() {
    asm volatile("cp.async.wait_group %0;" :: "n"(N));
}
__device__ __forceinline__ void mbar_init(uint32_t a, uint32_t cnt) {
    asm volatile("mbarrier.init.shared.b64 [%0], %1;" :: "r"(a), "r"(cnt) : "memory");
}
__device__ __forceinline__ void mbar_expect_tx(uint32_t a, uint32_t bytes) {
    asm volatile("mbarrier.arrive.expect_tx.shared.b64 _, [%0], %1;"
                 :: "r"(a), "r"(bytes) : "memory");
}
__device__ __forceinline__ void bulk_g2s(uint32_t dst, const void* src,
                                         uint32_t bytes, uint32_t mbar) {
    asm volatile(
        "cp.async.bulk.shared::cluster.global.mbarrier::complete_tx::bytes "
        "[%0], [%1], %2, [%3];"
        :: "r"(dst), "l"(src), "r"(bytes), "r"(mbar) : "memory");
}
__device__ __forceinline__ void mbar_wait(uint32_t mbar, uint32_t parity) {
    asm volatile(
        "{\n\t.reg .pred P1;\n\t"
        "WAIT_LOOP_%=:\n\t"
        "mbarrier.try_wait.parity.acquire.cta.shared::cta.b64 P1, [%0], %1, 0x989680;\n\t"
        "@P1 bra.uni WAIT_DONE_%=;\n\t"
        "bra.uni WAIT_LOOP_%=;\n\t"
        "WAIT_DONE_%=:\n\t}"
        :: "r"(mbar), "r"(parity) : "memory");
}
__device__ __forceinline__ void ldm_x4(uint32_t* r, uint32_t addr) {
    asm volatile("ldmatrix.sync.aligned.m8n8.x4.shared.b16 {%0,%1,%2,%3}, [%4];"
                 : "=r"(r[0]), "=r"(r[1]), "=r"(r[2]), "=r"(r[3]) : "r"(addr));
}
__device__ __forceinline__ void mma16816(float* c, const uint32_t* a,
                                         uint32_t b0, uint32_t b1) {
    asm volatile(
        "mma.sync.aligned.m16n8k16.row.col.f32.f16.f16.f32 "
        "{%0,%1,%2,%3}, {%4,%5,%6,%7}, {%8,%9}, {%0,%1,%2,%3};"
        : "+f"(c[0]), "+f"(c[1]), "+f"(c[2]), "+f"(c[3])
        : "r"(a[0]), "r"(a[1]), "r"(a[2]), "r"(a[3]), "r"(b0), "r"(b1));
}
__device__ __forceinline__ uint32_t h2(float v0, float v1) {
    __half2 h = __floats2half2_rn(v0, v1);
    return *(uint32_t*)&h;
}
__device__ __forceinline__ float2 h2f(uint32_t w) {
    return __half22float2(*(__half2*)&w);
}
// full 64x64 MMA block: 32 HMMA
__device__ __forceinline__ void mma_block(float (*c)[8][4],
                                          const uint32_t (*a)[4],
                                          const uint32_t (*b)[4]) {
#pragma unroll
    for (int i = 0; i < 4; i++)
#pragma unroll
        for (int j = 0; j < 4; j++) {
            mma16816(c[i][2 * j],     a[i], b[j][0], b[j][1]);
            mma16816(c[i][2 * j + 1], a[i], b[j][2], b[j][3]);
        }
}

// ======================= node MLP on fp16 HMMA =============================
constexpr int NA_STR  = 280;                     // halves
constexpr int NW_STR  = 264;                     // halves
constexpr int NOFF_W  = 64 * NA_STR * 2;         // 35840 B
constexpr int SMEM_N  = NOFF_W + 128 * NW_STR * 2;  // 103424 B

__global__ void __launch_bounds__(128, 2)
node_hmma_kernel(const float* __restrict__ x, const float* __restrict__ bx)
{
    extern __shared__ char smc[];
    const uint32_t sbase = smem_u32(smc);
    const int tid = threadIdx.x, wid = tid >> 5, lane = tid & 31;
    const long long r0 = (long long)blockIdx.x * 64;

    {
        const char* src = (const char*)g_wxpack;
        char* dst = smc + NOFF_W;
#pragma unroll
        for (int i = 0; i < 33; i++) {
            int idx = tid + i * 128;
            cp16b(dst + idx * 16, src + idx * 16);
        }
        cp_commit();
    }
    {
        const float4* x4 = (const float4*)(x + r0 * DN);
#pragma unroll
        for (int g = 0; g < 32; g++) {
            int f = tid + 128 * g;
            int row = f >> 6, col = f & 63;
            float4 v = x4[f];
            char* dst = smc + row * (NA_STR * 2) + col * 8;
            *(uint32_t*)(dst)     = h2(v.x, v.y);
            *(uint32_t*)(dst + 4) = h2(v.z, v.w);
        }
    }
    cp_wait<0>();
    __syncthreads();

    const int i7 = lane & 7;
    const int rowOff  = ((lane >> 3) & 1) * 8 + i7;
    const int aColOff = (lane >= 16) ? 16 : 0;
    const uint32_t aBase = sbase + (uint32_t)(16 * wid + rowOff) * (NA_STR * 2) + aColOff;
    const int nIdx  = ((lane >= 16) ? 8 : 0) + i7;
    const int bkOff = ((lane >> 3) & 1) * 16;
    uint32_t bB[8];
#pragma unroll
    for (int j = 0; j < 8; j++)
        bB[j] = sbase + NOFF_W + (uint32_t)(nIdx + 16 * j) * (NW_STR * 2) + bkOff;

    float c[16][4];
#pragma unroll
    for (int j = 0; j < 16; j++)
#pragma unroll
        for (int q = 0; q < 4; q++) c[j][q] = 0.f;

#pragma unroll 4
    for (int k = 0; k < 16; k++) {
        uint32_t a[4];
        ldm_x4(a, aBase + k * 32);
#pragma unroll
        for (int j = 0; j < 8; j++) {
            uint32_t b[4];
            ldm_x4(b, bB[j] + k * 32);
            mma16816(c[2 * j],     a, b[0], b[1]);
            mma16816(c[2 * j + 1], a, b[2], b[3]);
        }
    }

    const long long rb = r0 + 16 * wid + (lane >> 2);
#pragma unroll
    for (int j = 0; j < 16; j++) {
        int col = 8 * j + 2 * (lane & 3);
        float2 bb = __ldg((const float2*)(bx + col));
#pragma unroll
        for (int r8 = 0; r8 < 2; r8++) {
            float v0 = c[j][2 * r8]     + bb.x;
            float v1 = c[j][2 * r8 + 1] + bb.y;
            v0 = fmaxf(v0, 0.01f * v0);
            v1 = fmaxf(v1, 0.01f * v1);
            *(uint32_t*)((char*)g_hn + ((rb + 8 * r8) * IN + col) * 2) = h2(v0, v1);
        }
    }
}

// ======================= uv precompute: g_uv = g_hn @ W0' ==================
constexpr int UA_STR  = 272;                     // bytes (136 halves)
constexpr int UOFF_W  = 128 * UA_STR;            // 34816
constexpr int SMEM_UV = UOFF_W + 512 * UA_STR;   // 174080

__global__ void __launch_bounds__(256, 1)
uv_kernel()
{
    extern __shared__ char smc[];
    const uint32_t sbase = smem_u32(smc);
    const int tid = threadIdx.x, wid = tid >> 5, lane = tid & 31;
    const int mg = wid >> 2, ng = wid & 3;
    const int RB = 64 * mg, CB = 128 * ng;
    const long long r0 = (long long)blockIdx.x * 128;

    {
        const char* src = (const char*)(g_hn + r0 * IN);
#pragma unroll
        for (int i = 0; i < 8; i++) {
            int idx = tid + i * 256;
            int row = idx >> 4, col = idx & 15;
            cp16b(smc + row * UA_STR + col * 16, src + idx * 16);
        }
    }
    {
        const char* src = (const char*)g_w0p;
        char* dst = smc + UOFF_W;
#pragma unroll
        for (int i = 0; i < 34; i++) {
            int idx = tid + i * 256;
            cp16b(dst + idx * 16, src + idx * 16);
        }
    }
    cp_commit();
    cp_wait<0>();
    __syncthreads();

    const int i7 = lane & 7;
    const int rowOff  = ((lane >> 3) & 1) * 8 + i7;
    const int aColOff = (lane >= 16) ? 16 : 0;
    uint32_t aB[4];
#pragma unroll
    for (int i = 0; i < 4; i++)
        aB[i] = sbase + (uint32_t)(RB + 16 * i + rowOff) * UA_STR + aColOff;
    const int nIdx  = ((lane >= 16) ? 8 : 0) + i7;
    const int bkOff = ((lane >> 3) & 1) * 16;
    uint32_t bB[4];
#pragma unroll
    for (int j = 0; j < 4; j++)
        bB[j] = sbase + UOFF_W + (uint32_t)(CB + nIdx + 16 * j) * UA_STR + bkOff;

    float c[4][8][4];
#pragma unroll
    for (int i = 0; i < 4; i++)
#pragma unroll
        for (int j = 0; j < 8; j++)
#pragma unroll
            for (int q = 0; q < 4; q++) c[i][j][q] = 0.f;

#pragma unroll 2
    for (int k = 0; k < 8; k++) {
        uint32_t a[4][4], b[4][4];
#pragma unroll
        for (int j = 0; j < 4; j++) ldm_x4(b[j], bB[j] + k * 32);
#pragma unroll
        for (int i = 0; i < 4; i++) ldm_x4(a[i], aB[i] + k * 32);
        mma_block(c, a, b);
    }

#pragma unroll
    for (int i = 0; i < 4; i++) {
        const long long rb = r0 + RB + 16 * i + (lane >> 2);
#pragma unroll
        for (int j = 0; j < 8; j++) {
            int col = CB + 8 * j + 2 * (lane & 3);
            *(uint32_t*)((char*)g_uv + ((rb)     * 512 + col) * 2) = h2(c[i][j][0], c[i][j][1]);
            *(uint32_t*)((char*)g_uv + ((rb + 8) * 512 + col) * 2) = h2(c[i][j][2], c[i][j][3]);
        }
    }
}

// ======================= edge MLP on fp16 mma.sync =========================
constexpr int ASTRB  = 528;                      // A row stride: 264 fp16
constexpr int OFF_PT = 0;                        // classifier partials overlay A
constexpr int OFF_W  = 128 * ASTRB;              // 67584: 3 pair-slots x 40960
constexpr int OFF_MB = OFF_W + 3 * 2 * WCH;      // 190464 (3 mbarriers)
constexpr int SMEM_E = OFF_MB + 64;              // 190528

__device__ __forceinline__ uint32_t chunk_buf(uint32_t sbase, int c) {
    return sbase + OFF_W + (uint32_t)(((c >> 1) % 3) * (2 * WCH)) +
           (uint32_t)((c & 1) * WCH);
}
__device__ __forceinline__ void wait_pair(uint32_t sbase, int p) {
    mbar_wait(sbase + OFF_MB + (p % 3) * 8, (uint32_t)((p / 3) & 1));
}
__device__ __forceinline__ void fetch_pair(uint32_t sbase, int p) {
    uint32_t mb = sbase + OFF_MB + (p % 3) * 8;
    uint32_t bytes = (2 * p + 1 < NCHUNK) ? 2 * WCH : WCH;
    mbar_expect_tx(mb, bytes);
    bulk_g2s(sbase + OFF_W + (p % 3) * (2 * WCH),
             g_wpack + (size_t)(2 * p) * WCH, bytes, mb);
}

__global__ void __launch_bounds__(256, 1)
edge_hmma_kernel(const float* __restrict__ eattr,
                 const float* __restrict__ b0, const float* __restrict__ bmid,
                 const float* __restrict__ Wlast, const float* __restrict__ blast,
                 float* __restrict__ out, int E)
{
    extern __shared__ char smc[];
    const uint32_t sbase = smem_u32(smc);
    const int tid = threadIdx.x, wid = tid >> 5, lane = tid & 31;
    const int mg = wid >> 2, ng = wid & 3;        // 2 x 4 warp grid
    const int RB = 64 * mg, CB = 64 * ng;
    const long long e0 = (long long)blockIdx.x * 128;

    if (tid == 0)
        for (int i = 0; i < 3; i++) mbar_init(sbase + OFF_MB + i * 8, 1);
    __syncthreads();
    if (tid == 0) { fetch_pair(sbase, 0); fetch_pair(sbase, 1); fetch_pair(sbase, 2); }

    // ---------------- eattr -> A cols 0..15 ---------------------------------
    if (tid < 128) {
        long long ge = e0 + tid;
        const float4* ea4 = (const float4*)(eattr + ge * EA);
        uint4* ad = (uint4*)(smc + tid * ASTRB);
#pragma unroll
        for (int g = 0; g < 2; g++) {
            float4 f0 = ea4[2 * g], f1 = ea4[2 * g + 1];
            uint4 u;
            u.x = h2(f0.x, f0.y); u.y = h2(f0.z, f0.w);
            u.z = h2(f1.x, f1.y); u.w = h2(f1.z, f1.w);
            ad[g] = u;
        }
    }
    __syncthreads();

    // ---------------- per-thread invariant addresses ------------------------
    const int i7 = lane & 7;
    const int rowOff  = ((lane >> 3) & 1) * 8 + i7;
    const int aColOff = (lane >= 16) ? 16 : 0;            // bytes
    uint32_t aB[4];
#pragma unroll
    for (int i = 0; i < 4; i++)
        aB[i] = sbase + (uint32_t)(RB + 16 * i + rowOff) * ASTRB + aColOff;
    const int nIdx  = CB + ((lane >= 16) ? 8 : 0) + i7;
    const int bkOff = ((lane >> 3) & 1) * 16;             // bytes
    uint32_t bB[4];
#pragma unroll
    for (int j = 0; j < 4; j++) bB[j] = (uint32_t)(nIdx + 16 * j) * 80 + bkOff;

    float c[4][8][4];
#pragma unroll
    for (int i = 0; i < 4; i++)
#pragma unroll
        for (int j = 0; j < 8; j++)
#pragma unroll
            for (int q = 0; q < 4; q++) c[i][j][q] = 0.f;

    uint32_t bf0[4][4], bf1[4][4];

    // ---------------- L0: single k16 step (eattr @ W0e) ---------------------
    wait_pair(sbase, 0);
    {
        uint32_t a0[4][4];
        const uint32_t buf0 = chunk_buf(sbase, 0);
#pragma unroll
        for (int j = 0; j < 4; j++) ldm_x4(bf0[j], buf0 + bB[j]);
#pragma unroll
        for (int i = 0; i < 4; i++) ldm_x4(a0[i], aB[i]);   // eattr cols 0-15
        mma_block(c, a0, bf0);
        const uint32_t buf1 = chunk_buf(sbase, 1);          // pair 0, present
#pragma unroll
        for (int j = 0; j < 4; j++) ldm_x4(bf0[j], buf1 + bB[j]);
    }
    __syncthreads();   // all eattr A-reads done before overwrite

    // L0 epilogue: C += u[row] + v[col] + b0, leaky -> A plane; zero C
    {
#pragma unroll
        for (int i = 0; i < 4; i++) {
            const int row0 = RB + 16 * i + (lane >> 2);
            const long long ge0 = e0 + row0, ge1 = ge0 + 8;
            const char* u0 = (const char*)(g_uv + (size_t)__ldg(g_ei + ge0) * 512);
            const char* v0 = (const char*)(g_uv + (size_t)__ldg(g_ei + E + ge0) * 512 + 256);
            const char* u1 = (const char*)(g_uv + (size_t)__ldg(g_ei + ge1) * 512);
            const char* v1 = (const char*)(g_uv + (size_t)__ldg(g_ei + E + ge1) * 512 + 256);
#pragma unroll
            for (int j = 0; j < 8; j++) {
                const int col = CB + 8 * j + 2 * (lane & 3);
                float2 bb = __ldg((const float2*)(b0 + col));
                float2 su0 = h2f(__ldg((const uint32_t*)(u0 + col * 2)));
                float2 sv0 = h2f(__ldg((const uint32_t*)(v0 + col * 2)));
                float2 su1 = h2f(__ldg((const uint32_t*)(u1 + col * 2)));
                float2 sv1 = h2f(__ldg((const uint32_t*)(v1 + col * 2)));
                float v0f = c[i][j][0] + su0.x + sv0.x + bb.x;
                float v1f = c[i][j][1] + su0.y + sv0.y + bb.y;
                float v2f = c[i][j][2] + su1.x + sv1.x + bb.x;
                float v3f = c[i][j][3] + su1.y + sv1.y + bb.y;
                v0f = fmaxf(v0f, 0.01f * v0f); v1f = fmaxf(v1f, 0.01f * v1f);
                v2f = fmaxf(v2f, 0.01f * v2f); v3f = fmaxf(v3f, 0.01f * v3f);
                char* p0 = smc + row0 * ASTRB + col * 2;
                *(uint32_t*)(p0)             = h2(v0f, v1f);
                *(uint32_t*)(p0 + 8 * ASTRB) = h2(v2f, v3f);
                c[i][j][0] = 0.f; c[i][j][1] = 0.f;
                c[i][j][2] = 0.f; c[i][j][3] = 0.f;
            }
        }
    }
    __syncthreads();

    // ---------------- layers 1..8: 4 pair-iterations each -------------------
    int t = 0;   // iteration index 0..31; consumes chunks (2t+1, 2t+2)
#pragma unroll 1
    for (int L = 1; L <= 8; L++) {
#pragma unroll 1
        for (int p = 0; p < 4; p++) {
            const int ca = 2 * t + 1, cb = ca + 1, nc = cb + 1;
            const int kA = p * 128;
            const uint32_t bufA = chunk_buf(sbase, ca);
            uint32_t a[4][4];

#pragma unroll
            for (int j = 0; j < 4; j++) ldm_x4(bf1[j], bufA + bB[j] + 32);
#pragma unroll
            for (int i = 0; i < 4; i++) ldm_x4(a[i], aB[i] + kA);
            mma_block(c, a, bf0);
            wait_pair(sbase, t + 1);                       // pair of cb
            const uint32_t bufB = chunk_buf(sbase, cb);
#pragma unroll
            for (int i = 0; i < 4; i++) ldm_x4(a[i], aB[i] + kA + 32);
#pragma unroll
            for (int j = 0; j < 4; j++) ldm_x4(bf0[j], bufB + bB[j]);
            mma_block(c, a, bf1);
#pragma unroll
            for (int j = 0; j < 4; j++) ldm_x4(bf1[j], bufB + bB[j] + 32);
#pragma unroll
            for (int i = 0; i < 4; i++) ldm_x4(a[i], aB[i] + kA + 64);
            mma_block(c, a, bf0);
#pragma unroll
            for (int i = 0; i < 4; i++) ldm_x4(a[i], aB[i] + kA + 96);
            if (nc < NCHUNK) {
                const uint32_t bufN = chunk_buf(sbase, nc);  // pair t+1, present
#pragma unroll
                for (int j = 0; j < 4; j++) ldm_x4(bf0[j], bufN + bB[j]);
            }
            mma_block(c, a, bf1);

            __syncthreads();                // pair t fully consumed by all warps
            if (tid == 0 && t + 3 <= 32) fetch_pair(sbase, t + 3);
            t++;
        }

        if (L < 8) {
            const float* bias = bmid + (L - 1) * 256;
#pragma unroll
            for (int i = 0; i < 4; i++) {
                const int row0 = RB + 16 * i + (lane >> 2);
#pragma unroll
                for (int j = 0; j < 8; j++) {
                    const int col = CB + 8 * j + 2 * (lane & 3);
                    float2 bb = __ldg((const float2*)(bias + col));
                    float v0 = c[i][j][0] + bb.x, v1 = c[i][j][1] + bb.y;
                    float v2 = c[i][j][2] + bb.x, v3 = c[i][j][3] + bb.y;
                    v0 = fmaxf(v0, 0.01f * v0); v1 = fmaxf(v1, 0.01f * v1);
                    v2 = fmaxf(v2, 0.01f * v2); v3 = fmaxf(v3, 0.01f * v3);
                    char* p0 = smc + row0 * ASTRB + col * 2;
                    *(uint32_t*)(p0)             = h2(v0, v1);
                    *(uint32_t*)(p0 + 8 * ASTRB) = h2(v2, v3);
                    c[i][j][0] = 0.f; c[i][j][1] = 0.f;
                    c[i][j][2] = 0.f; c[i][j][3] = 0.f;
                }
            }
            __syncthreads();
        }
    }

    // ---------------- classifier + log_softmax ------------------------------
    {
        const float* bias = bmid + 7 * 256;
        float p[4][2][3];
#pragma unroll
        for (int i = 0; i < 4; i++)
#pragma unroll
            for (int h = 0; h < 2; h++)
                p[i][h][0] = p[i][h][1] = p[i][h][2] = 0.f;
#pragma unroll
        for (int i = 0; i < 4; i++) {
#pragma unroll
            for (int j = 0; j < 8; j++) {
                const int col = CB + 8 * j + 2 * (lane & 3);
                float2 bb = __ldg((const float2*)(bias + col));
                float v0 = c[i][j][0] + bb.x, v1 = c[i][j][1] + bb.y;
                float v2 = c[i][j][2] + bb.x, v3 = c[i][j][3] + bb.y;
                v0 = fmaxf(v0, 0.01f * v0); v1 = fmaxf(v1, 0.01f * v1);
                v2 = fmaxf(v2, 0.01f * v2); v3 = fmaxf(v3, 0.01f * v3);
                const float* w0 = Wlast + col * 3;
#pragma unroll
                for (int k = 0; k < 3; k++) {
                    float wa = __ldg(w0 + k), wb2 = __ldg(w0 + 3 + k);
                    p[i][0][k] = fmaf(v0, wa, fmaf(v1, wb2, p[i][0][k]));
                    p[i][1][k] = fmaf(v2, wa, fmaf(v3, wb2, p[i][1][k]));
                }
            }
        }
#pragma unroll
        for (int i = 0; i < 4; i++)
#pragma unroll
            for (int h = 0; h < 2; h++)
#pragma unroll
                for (int k = 0; k < 3; k++) {
                    float v = p[i][h][k];
                    v += __shfl_xor_sync(0xffffffffu, v, 1);
                    v += __shfl_xor_sync(0xffffffffu, v, 2);
                    p[i][h][k] = v;
                }
        float* pt = (float*)(smc + OFF_PT);   // overlay A plane
        __syncthreads();                       // A-plane reads all done
        if ((lane & 3) == 0) {
#pragma unroll
            for (int i = 0; i < 4; i++)
#pragma unroll
                for (int h = 0; h < 2; h++) {
                    int row = RB + 16 * i + (lane >> 2) + 8 * h;
#pragma unroll
                    for (int k = 0; k < 3; k++)
                        pt[(row * 4 + ng) * 3 + k] = p[i][h][k];
                }
        }
    }
    __syncthreads();
    if (tid < 128) {
        const float* pt = (const float*)(smc + OFF_PT);
        float l[3];
#pragma unroll
        for (int k = 0; k < 3; k++) {
            float s = __ldg(blast + k);
#pragma unroll
            for (int g = 0; g < 4; g++) s += pt[(tid * 4 + g) * 3 + k];
            l[k] = s;
        }
        float mx  = fmaxf(l[0], fmaxf(l[1], l[2]));
        float lse = mx + logf(expf(l[0] - mx) + expf(l[1] - mx) + expf(l[2] - mx));
        float* o = out + (e0 + tid) * NOUT;
        o[0] = l[0] - lse; o[1] = l[1] - lse; o[2] = l[2] - lse;
    }
}

// ===========================================================================
extern "C" void kernel_launch(void* const* d_in, const int* in_sizes, int n_in,
                              void* d_out, int out_size)
{
    const float* x      = (const float*)d_in[0];
    const int*   ei_raw = (const int*)d_in[1];
    const float* eattr  = (const float*)d_in[2];
    const float* Wx     = (const float*)d_in[3];
    const float* bx     = (const float*)d_in[4];
    const float* W0     = (const float*)d_in[5];
    const float* b0     = (const float*)d_in[6];
    const float* Wmid   = (const float*)d_in[7];
    const float* bmid   = (const float*)d_in[8];
    const float* Wlast  = (const float*)d_in[9];
    const float* blast  = (const float*)d_in[10];
    float* out = (float*)d_out;

    const int N  = in_sizes[0] / DN;
    const int E  = in_sizes[2] / EA;
    const int n2 = 2 * E;
    const int nconv = (n2 + 255) / 256;

    cudaFuncSetAttribute(node_hmma_kernel,
                         cudaFuncAttributeMaxDynamicSharedMemorySize, SMEM_N);
    cudaFuncSetAttribute(uv_kernel,
                         cudaFuncAttributeMaxDynamicSharedMemorySize, SMEM_UV);
    cudaFuncSetAttribute(edge_hmma_kernel,
                         cudaFuncAttributeMaxDynamicSharedMemorySize, SMEM_E);

    prep_all<<<nconv + NPACK_BLK + NWX_BLK + NW0P_BLK, 256>>>(ei_raw, W0, Wmid, Wx, n2);
    node_hmma_kernel<<<N / 64, 128, SMEM_N>>>(x, bx);
    uv_kernel<<<N / 128, 256, SMEM_UV>>>();
    edge_hmma_kernel<<<E / 128, 256, SMEM_E>>>(eattr, b0, bmid, Wlast, blast,
                                               out, E);
}

// round 13
// speedup vs baseline: 1.1309x; 1.0092x over previous
#include <cuda_runtime.h>
#include <cuda_fp16.h>
#include <cstdint>

// ---------------------------------------------------------------------------
// EdgeClassNet, fully fp16-HMMA. R13: edge kernel widened to 512 threads
// (16 warps, 4/SMSP, warp tile 32x64) to hide HMMA/LDSM latency; everything
// else identical to R12 (uv precompute, 3 pair-slot bulk weight ring).
// ---------------------------------------------------------------------------

constexpr int DN   = 256;   // node input dim
constexpr int IN   = 128;   // node hidden dim
constexpr int EA   = 16;
constexpr int NOUT = 3;

constexpr int MAXN = 65536;
constexpr int MAXE = 262144;

// 65 weight chunks: chunk 0 = W0e (eattr rows, K=16), chunks 1..64 = 8 mid
// layers x 8. Each chunk image: [256 n][40 k] fp16 = 20480 B. Paired fetches.
constexpr int NCHUNK = 65;
constexpr int WCH    = 20480;

__device__ __half g_hn[MAXN * IN];                 // 16 MB node hidden (fp16)
__device__ __half g_uv[MAXN * 512];                // 67 MB u|v partials (fp16)
__device__ int    g_ei[2 * MAXE];
__device__ __align__(16) unsigned char g_wpack[NCHUNK * WCH];
__device__ __align__(16) __half g_wxpack[128 * 264];   // node W: [n][k pad]
__device__ __align__(16) __half g_w0p[512 * 136];      // W0' : [512 n][136 k pad]

// ======================= merged prep kernel ================================
constexpr int NPACK_BLK = (NCHUNK * 256 * 40) / 256;   // 2600
constexpr int NWX_BLK   = (128 * 264) / 256;           // 132
constexpr int NW0P_BLK  = (512 * 136) / 256;           // 272

__global__ void prep_all(const int* __restrict__ ei_raw,
                         const float* __restrict__ W0,
                         const float* __restrict__ Wmid,
                         const float* __restrict__ Wx, int n2e)
{
    const int nconv = (n2e + 255) >> 8;
    const int b = blockIdx.x;
    if (b < nconv) {
        int nz = __syncthreads_or(ei_raw[2 * threadIdx.x + 1] != 0);
        int i = b * 256 + threadIdx.x;
        if (i < n2e) g_ei[i] = nz ? ei_raw[i] : ei_raw[2 * i];
    } else if (b < nconv + NPACK_BLK) {
        int idx = (b - nconv) * 256 + threadIdx.x;     // over 65*256*40
        int klocal = idx % 40;
        int n  = (idx / 40) & 255;
        int ch = idx / (40 * 256);
        float w = 0.f;
        if (ch == 0) {
            if (klocal < 16) w = W0[(256 + klocal) * 256 + n];
        } else {
            int L = (ch - 1) >> 3, cc = (ch - 1) & 7;
            int k = cc * 32 + klocal;
            if (klocal < 32) w = Wmid[L * 65536 + k * 256 + n];
        }
        *(__half*)(g_wpack + (size_t)ch * WCH + n * 80 + klocal * 2) = __float2half_rn(w);
    } else if (b < nconv + NPACK_BLK + NWX_BLK) {
        int idx = (b - nconv - NPACK_BLK) * 256 + threadIdx.x;  // over 128*264
        int n = idx / 264, k = idx % 264;
        g_wxpack[idx] = __float2half_rn(k < 256 ? Wx[k * 128 + n] : 0.f);
    } else {
        int idx = (b - nconv - NPACK_BLK - NWX_BLK) * 256 + threadIdx.x;  // 512*136
        int m = idx / 136, k = idx % 136;
        float w = 0.f;
        if (k < 128)
            w = (m < 256) ? W0[k * 256 + m] : W0[(128 + k) * 256 + (m - 256)];
        g_w0p[idx] = __float2half_rn(w);
    }
}

// ======================= PTX helpers =======================================
__device__ __forceinline__ uint32_t smem_u32(const void* p) {
    uint32_t a;
    asm("{ .reg .u64 t; cvta.to.shared.u64 t, %1; cvt.u32.u64 %0, t; }"
        : "=r"(a) : "l"(p));
    return a;
}
__device__ __forceinline__ void cp16b(char* dst, const char* src) {
    unsigned u = (unsigned)__cvta_generic_to_shared(dst);
    asm volatile("cp.async.cg.shared.global [%0], [%1], 16;" :: "r"(u), "l"(src));
}
__device__ __forceinline__ void cp_commit() { asm volatile("cp.async.commit_group;"); }
template<int N> __device__ __forceinline__ void cp_wait() {
    asm volatile("cp.async.wait_group %0;" :: "n"(N));
}
__device__ __forceinline__ void mbar_init(uint32_t a, uint32_t cnt) {
    asm volatile("mbarrier.init.shared.b64 [%0], %1;" :: "r"(a), "r"(cnt) : "memory");
}
__device__ __forceinline__ void mbar_expect_tx(uint32_t a, uint32_t bytes) {
    asm volatile("mbarrier.arrive.expect_tx.shared.b64 _, [%0], %1;"
                 :: "r"(a), "r"(bytes) : "memory");
}
__device__ __forceinline__ void bulk_g2s(uint32_t dst, const void* src,
                                         uint32_t bytes, uint32_t mbar) {
    asm volatile(
        "cp.async.bulk.shared::cluster.global.mbarrier::complete_tx::bytes "
        "[%0], [%1], %2, [%3];"
        :: "r"(dst), "l"(src), "r"(bytes), "r"(mbar) : "memory");
}
__device__ __forceinline__ void mbar_wait(uint32_t mbar, uint32_t parity) {
    asm volatile(
        "{\n\t.reg .pred P1;\n\t"
        "WAIT_LOOP_%=:\n\t"
        "mbarrier.try_wait.parity.acquire.cta.shared::cta.b64 P1, [%0], %1, 0x989680;\n\t"
        "@P1 bra.uni WAIT_DONE_%=;\n\t"
        "bra.uni WAIT_LOOP_%=;\n\t"
        "WAIT_DONE_%=:\n\t}"
        :: "r"(mbar), "r"(parity) : "memory");
}
__device__ __forceinline__ void ldm_x4(uint32_t* r, uint32_t addr) {
    asm volatile("ldmatrix.sync.aligned.m8n8.x4.shared.b16 {%0,%1,%2,%3}, [%4];"
                 : "=r"(r[0]), "=r"(r[1]), "=r"(r[2]), "=r"(r[3]) : "r"(addr));
}
__device__ __forceinline__ void mma16816(float* c, const uint32_t* a,
                                         uint32_t b0, uint32_t b1) {
    asm volatile(
        "mma.sync.aligned.m16n8k16.row.col.f32.f16.f16.f32 "
        "{%0,%1,%2,%3}, {%4,%5,%6,%7}, {%8,%9}, {%0,%1,%2,%3};"
        : "+f"(c[0]), "+f"(c[1]), "+f"(c[2]), "+f"(c[3])
        : "r"(a[0]), "r"(a[1]), "r"(a[2]), "r"(a[3]), "r"(b0), "r"(b1));
}
__device__ __forceinline__ uint32_t h2(float v0, float v1) {
    __half2 h = __floats2half2_rn(v0, v1);
    return *(uint32_t*)&h;
}
__device__ __forceinline__ float2 h2f(uint32_t w) {
    return __half22float2(*(__half2*)&w);
}
// 32x64 MMA block: 16 HMMA (2 i-tiles x 4 j-pairs)
__device__ __forceinline__ void mma_block2(float (*c)[8][4],
                                           const uint32_t (*a)[4],
                                           const uint32_t (*b)[4]) {
#pragma unroll
    for (int i = 0; i < 2; i++)
#pragma unroll
        for (int j = 0; j < 4; j++) {
            mma16816(c[i][2 * j],     a[i], b[j][0], b[j][1]);
            mma16816(c[i][2 * j + 1], a[i], b[j][2], b[j][3]);
        }
}

// ======================= node MLP on fp16 HMMA =============================
constexpr int NA_STR  = 280;                     // halves
constexpr int NW_STR  = 264;                     // halves
constexpr int NOFF_W  = 64 * NA_STR * 2;         // 35840 B
constexpr int SMEM_N  = NOFF_W + 128 * NW_STR * 2;  // 103424 B

__global__ void __launch_bounds__(128, 2)
node_hmma_kernel(const float* __restrict__ x, const float* __restrict__ bx)
{
    extern __shared__ char smc[];
    const uint32_t sbase = smem_u32(smc);
    const int tid = threadIdx.x, wid = tid >> 5, lane = tid & 31;
    const long long r0 = (long long)blockIdx.x * 64;

    {
        const char* src = (const char*)g_wxpack;
        char* dst = smc + NOFF_W;
#pragma unroll
        for (int i = 0; i < 33; i++) {
            int idx = tid + i * 128;
            cp16b(dst + idx * 16, src + idx * 16);
        }
        cp_commit();
    }
    {
        const float4* x4 = (const float4*)(x + r0 * DN);
#pragma unroll
        for (int g = 0; g < 32; g++) {
            int f = tid + 128 * g;
            int row = f >> 6, col = f & 63;
            float4 v = x4[f];
            char* dst = smc + row * (NA_STR * 2) + col * 8;
            *(uint32_t*)(dst)     = h2(v.x, v.y);
            *(uint32_t*)(dst + 4) = h2(v.z, v.w);
        }
    }
    cp_wait<0>();
    __syncthreads();

    const int i7 = lane & 7;
    const int rowOff  = ((lane >> 3) & 1) * 8 + i7;
    const int aColOff = (lane >= 16) ? 16 : 0;
    const uint32_t aBase = sbase + (uint32_t)(16 * wid + rowOff) * (NA_STR * 2) + aColOff;
    const int nIdx  = ((lane >= 16) ? 8 : 0) + i7;
    const int bkOff = ((lane >> 3) & 1) * 16;
    uint32_t bB[8];
#pragma unroll
    for (int j = 0; j < 8; j++)
        bB[j] = sbase + NOFF_W + (uint32_t)(nIdx + 16 * j) * (NW_STR * 2) + bkOff;

    float c[16][4];
#pragma unroll
    for (int j = 0; j < 16; j++)
#pragma unroll
        for (int q = 0; q < 4; q++) c[j][q] = 0.f;

#pragma unroll 4
    for (int k = 0; k < 16; k++) {
        uint32_t a[4];
        ldm_x4(a, aBase + k * 32);
#pragma unroll
        for (int j = 0; j < 8; j++) {
            uint32_t b[4];
            ldm_x4(b, bB[j] + k * 32);
            mma16816(c[2 * j],     a, b[0], b[1]);
            mma16816(c[2 * j + 1], a, b[2], b[3]);
        }
    }

    const long long rb = r0 + 16 * wid + (lane >> 2);
#pragma unroll
    for (int j = 0; j < 16; j++) {
        int col = 8 * j + 2 * (lane & 3);
        float2 bb = __ldg((const float2*)(bx + col));
#pragma unroll
        for (int r8 = 0; r8 < 2; r8++) {
            float v0 = c[j][2 * r8]     + bb.x;
            float v1 = c[j][2 * r8 + 1] + bb.y;
            v0 = fmaxf(v0, 0.01f * v0);
            v1 = fmaxf(v1, 0.01f * v1);
            *(uint32_t*)((char*)g_hn + ((rb + 8 * r8) * IN + col) * 2) = h2(v0, v1);
        }
    }
}

// ======================= uv precompute: g_uv = g_hn @ W0' ==================
constexpr int UA_STR  = 272;                     // bytes (136 halves)
constexpr int UOFF_W  = 128 * UA_STR;            // 34816
constexpr int SMEM_UV = UOFF_W + 512 * UA_STR;   // 174080

__global__ void __launch_bounds__(256, 1)
uv_kernel()
{
    extern __shared__ char smc[];
    const uint32_t sbase = smem_u32(smc);
    const int tid = threadIdx.x, wid = tid >> 5, lane = tid & 31;
    const int mg = wid >> 2, ng = wid & 3;
    const int RB = 64 * mg, CB = 128 * ng;
    const long long r0 = (long long)blockIdx.x * 128;

    {
        const char* src = (const char*)(g_hn + r0 * IN);
#pragma unroll
        for (int i = 0; i < 8; i++) {
            int idx = tid + i * 256;
            int row = idx >> 4, col = idx & 15;
            cp16b(smc + row * UA_STR + col * 16, src + idx * 16);
        }
    }
    {
        const char* src = (const char*)g_w0p;
        char* dst = smc + UOFF_W;
#pragma unroll
        for (int i = 0; i < 34; i++) {
            int idx = tid + i * 256;
            cp16b(dst + idx * 16, src + idx * 16);
        }
    }
    cp_commit();
    cp_wait<0>();
    __syncthreads();

    const int i7 = lane & 7;
    const int rowOff  = ((lane >> 3) & 1) * 8 + i7;
    const int aColOff = (lane >= 16) ? 16 : 0;
    uint32_t aB[4];
#pragma unroll
    for (int i = 0; i < 4; i++)
        aB[i] = sbase + (uint32_t)(RB + 16 * i + rowOff) * UA_STR + aColOff;
    const int nIdx  = ((lane >= 16) ? 8 : 0) + i7;
    const int bkOff = ((lane >> 3) & 1) * 16;
    uint32_t bB[4];
#pragma unroll
    for (int j = 0; j < 4; j++)
        bB[j] = sbase + UOFF_W + (uint32_t)(CB + nIdx + 16 * j) * UA_STR + bkOff;

    float c[4][8][4];
#pragma unroll
    for (int i = 0; i < 4; i++)
#pragma unroll
        for (int j = 0; j < 8; j++)
#pragma unroll
            for (int q = 0; q < 4; q++) c[i][j][q] = 0.f;

#pragma unroll 2
    for (int k = 0; k < 8; k++) {
        uint32_t a[4][4], b[4][4];
#pragma unroll
        for (int j = 0; j < 4; j++) ldm_x4(b[j], bB[j] + k * 32);
#pragma unroll
        for (int i = 0; i < 4; i++) ldm_x4(a[i], aB[i] + k * 32);
#pragma unroll
        for (int i = 0; i < 4; i++)
#pragma unroll
            for (int j = 0; j < 4; j++) {
                mma16816(c[i][2 * j],     a[i], b[j][0], b[j][1]);
                mma16816(c[i][2 * j + 1], a[i], b[j][2], b[j][3]);
            }
    }

#pragma unroll
    for (int i = 0; i < 4; i++) {
        const long long rb = r0 + RB + 16 * i + (lane >> 2);
#pragma unroll
        for (int j = 0; j < 8; j++) {
            int col = CB + 8 * j + 2 * (lane & 3);
            *(uint32_t*)((char*)g_uv + ((rb)     * 512 + col) * 2) = h2(c[i][j][0], c[i][j][1]);
            *(uint32_t*)((char*)g_uv + ((rb + 8) * 512 + col) * 2) = h2(c[i][j][2], c[i][j][3]);
        }
    }
}

// ======================= edge MLP on fp16 mma.sync (512 thr) ===============
constexpr int ASTRB  = 528;                      // A row stride: 264 fp16
constexpr int OFF_PT = 0;                        // classifier partials overlay A
constexpr int OFF_W  = 128 * ASTRB;              // 67584: 3 pair-slots x 40960
constexpr int OFF_MB = OFF_W + 3 * 2 * WCH;      // 190464 (3 mbarriers)
constexpr int SMEM_E = OFF_MB + 64;              // 190528

__device__ __forceinline__ uint32_t chunk_buf(uint32_t sbase, int c) {
    return sbase + OFF_W + (uint32_t)(((c >> 1) % 3) * (2 * WCH)) +
           (uint32_t)((c & 1) * WCH);
}
__device__ __forceinline__ void wait_pair(uint32_t sbase, int p) {
    mbar_wait(sbase + OFF_MB + (p % 3) * 8, (uint32_t)((p / 3) & 1));
}
__device__ __forceinline__ void fetch_pair(uint32_t sbase, int p) {
    uint32_t mb = sbase + OFF_MB + (p % 3) * 8;
    uint32_t bytes = (2 * p + 1 < NCHUNK) ? 2 * WCH : WCH;
    mbar_expect_tx(mb, bytes);
    bulk_g2s(sbase + OFF_W + (p % 3) * (2 * WCH),
             g_wpack + (size_t)(2 * p) * WCH, bytes, mb);
}

__global__ void __launch_bounds__(512, 1)
edge_hmma_kernel(const float* __restrict__ eattr,
                 const float* __restrict__ b0, const float* __restrict__ bmid,
                 const float* __restrict__ Wlast, const float* __restrict__ blast,
                 float* __restrict__ out, int E)
{
    extern __shared__ char smc[];
    const uint32_t sbase = smem_u32(smc);
    const int tid = threadIdx.x, wid = tid >> 5, lane = tid & 31;
    const int mg = wid >> 2, ng = wid & 3;        // 4 x 4 warp grid
    const int RB = 32 * mg, CB = 64 * ng;
    const long long e0 = (long long)blockIdx.x * 128;

    if (tid == 0)
        for (int i = 0; i < 3; i++) mbar_init(sbase + OFF_MB + i * 8, 1);
    __syncthreads();
    if (tid == 0) { fetch_pair(sbase, 0); fetch_pair(sbase, 1); fetch_pair(sbase, 2); }

    // ---------------- eattr -> A cols 0..15 ---------------------------------
    if (tid < 128) {
        long long ge = e0 + tid;
        const float4* ea4 = (const float4*)(eattr + ge * EA);
        uint4* ad = (uint4*)(smc + tid * ASTRB);
#pragma unroll
        for (int g = 0; g < 2; g++) {
            float4 f0 = ea4[2 * g], f1 = ea4[2 * g + 1];
            uint4 u;
            u.x = h2(f0.x, f0.y); u.y = h2(f0.z, f0.w);
            u.z = h2(f1.x, f1.y); u.w = h2(f1.z, f1.w);
            ad[g] = u;
        }
    }
    __syncthreads();

    // ---------------- per-thread invariant addresses ------------------------
    const int i7 = lane & 7;
    const int rowOff  = ((lane >> 3) & 1) * 8 + i7;
    const int aColOff = (lane >= 16) ? 16 : 0;            // bytes
    uint32_t aB[2];
#pragma unroll
    for (int i = 0; i < 2; i++)
        aB[i] = sbase + (uint32_t)(RB + 16 * i + rowOff) * ASTRB + aColOff;
    const int nIdx  = CB + ((lane >= 16) ? 8 : 0) + i7;
    const int bkOff = ((lane >> 3) & 1) * 16;             // bytes
    uint32_t bB[4];
#pragma unroll
    for (int j = 0; j < 4; j++) bB[j] = (uint32_t)(nIdx + 16 * j) * 80 + bkOff;

    float c[2][8][4];
#pragma unroll
    for (int i = 0; i < 2; i++)
#pragma unroll
        for (int j = 0; j < 8; j++)
#pragma unroll
            for (int q = 0; q < 4; q++) c[i][j][q] = 0.f;

    uint32_t bf0[4][4], bf1[4][4];

    // ---------------- L0: single k16 step (eattr @ W0e) ---------------------
    wait_pair(sbase, 0);
    {
        uint32_t a0[2][4];
        const uint32_t buf0 = chunk_buf(sbase, 0);
#pragma unroll
        for (int j = 0; j < 4; j++) ldm_x4(bf0[j], buf0 + bB[j]);
#pragma unroll
        for (int i = 0; i < 2; i++) ldm_x4(a0[i], aB[i]);   // eattr cols 0-15
        mma_block2(c, a0, bf0);
        const uint32_t buf1 = chunk_buf(sbase, 1);          // pair 0, present
#pragma unroll
        for (int j = 0; j < 4; j++) ldm_x4(bf0[j], buf1 + bB[j]);
    }
    __syncthreads();   // all eattr A-reads done before overwrite

    // L0 epilogue: C += u[row] + v[col] + b0, leaky -> A plane; zero C
    {
#pragma unroll
        for (int i = 0; i < 2; i++) {
            const int row0 = RB + 16 * i + (lane >> 2);
            const long long ge0 = e0 + row0, ge1 = ge0 + 8;
            const char* u0 = (const char*)(g_uv + (size_t)__ldg(g_ei + ge0) * 512);
            const char* v0 = (const char*)(g_uv + (size_t)__ldg(g_ei + E + ge0) * 512 + 256);
            const char* u1 = (const char*)(g_uv + (size_t)__ldg(g_ei + ge1) * 512);
            const char* v1 = (const char*)(g_uv + (size_t)__ldg(g_ei + E + ge1) * 512 + 256);
#pragma unroll
            for (int j = 0; j < 8; j++) {
                const int col = CB + 8 * j + 2 * (lane & 3);
                float2 bb = __ldg((const float2*)(b0 + col));
                float2 su0 = h2f(__ldg((const uint32_t*)(u0 + col * 2)));
                float2 sv0 = h2f(__ldg((const uint32_t*)(v0 + col * 2)));
                float2 su1 = h2f(__ldg((const uint32_t*)(u1 + col * 2)));
                float2 sv1 = h2f(__ldg((const uint32_t*)(v1 + col * 2)));
                float v0f = c[i][j][0] + su0.x + sv0.x + bb.x;
                float v1f = c[i][j][1] + su0.y + sv0.y + bb.y;
                float v2f = c[i][j][2] + su1.x + sv1.x + bb.x;
                float v3f = c[i][j][3] + su1.y + sv1.y + bb.y;
                v0f = fmaxf(v0f, 0.01f * v0f); v1f = fmaxf(v1f, 0.01f * v1f);
                v2f = fmaxf(v2f, 0.01f * v2f); v3f = fmaxf(v3f, 0.01f * v3f);
                char* p0 = smc + row0 * ASTRB + col * 2;
                *(uint32_t*)(p0)             = h2(v0f, v1f);
                *(uint32_t*)(p0 + 8 * ASTRB) = h2(v2f, v3f);
                c[i][j][0] = 0.f; c[i][j][1] = 0.f;
                c[i][j][2] = 0.f; c[i][j][3] = 0.f;
            }
        }
    }
    __syncthreads();

    // ---------------- layers 1..8: 4 pair-iterations each -------------------
    int t = 0;   // iteration index 0..31; consumes chunks (2t+1, 2t+2)
#pragma unroll 1
    for (int L = 1; L <= 8; L++) {
#pragma unroll 1
        for (int p = 0; p < 4; p++) {
            const int ca = 2 * t + 1, cb = ca + 1, nc = cb + 1;
            const int kA = p * 128;
            const uint32_t bufA = chunk_buf(sbase, ca);
            uint32_t a[2][4];

#pragma unroll
            for (int j = 0; j < 4; j++) ldm_x4(bf1[j], bufA + bB[j] + 32);
#pragma unroll
            for (int i = 0; i < 2; i++) ldm_x4(a[i], aB[i] + kA);
            mma_block2(c, a, bf0);
            wait_pair(sbase, t + 1);                       // pair of cb
            const uint32_t bufB = chunk_buf(sbase, cb);
#pragma unroll
            for (int i = 0; i < 2; i++) ldm_x4(a[i], aB[i] + kA + 32);
#pragma unroll
            for (int j = 0; j < 4; j++) ldm_x4(bf0[j], bufB + bB[j]);
            mma_block2(c, a, bf1);
#pragma unroll
            for (int j = 0; j < 4; j++) ldm_x4(bf1[j], bufB + bB[j] + 32);
#pragma unroll
            for (int i = 0; i < 2; i++) ldm_x4(a[i], aB[i] + kA + 64);
            mma_block2(c, a, bf0);
#pragma unroll
            for (int i = 0; i < 2; i++) ldm_x4(a[i], aB[i] + kA + 96);
            if (nc < NCHUNK) {
                const uint32_t bufN = chunk_buf(sbase, nc);  // pair t+1, present
#pragma unroll
                for (int j = 0; j < 4; j++) ldm_x4(bf0[j], bufN + bB[j]);
            }
            mma_block2(c, a, bf1);

            __syncthreads();                // pair t fully consumed by all warps
            if (tid == 0 && t + 3 <= 32) fetch_pair(sbase, t + 3);
            t++;
        }

        if (L < 8) {
            const float* bias = bmid + (L - 1) * 256;
#pragma unroll
            for (int i = 0; i < 2; i++) {
                const int row0 = RB + 16 * i + (lane >> 2);
#pragma unroll
                for (int j = 0; j < 8; j++) {
                    const int col = CB + 8 * j + 2 * (lane & 3);
                    float2 bb = __ldg((const float2*)(bias + col));
                    float v0 = c[i][j][0] + bb.x, v1 = c[i][j][1] + bb.y;
                    float v2 = c[i][j][2] + bb.x, v3 = c[i][j][3] + bb.y;
                    v0 = fmaxf(v0, 0.01f * v0); v1 = fmaxf(v1, 0.01f * v1);
                    v2 = fmaxf(v2, 0.01f * v2); v3 = fmaxf(v3, 0.01f * v3);
                    char* p0 = smc + row0 * ASTRB + col * 2;
                    *(uint32_t*)(p0)             = h2(v0, v1);
                    *(uint32_t*)(p0 + 8 * ASTRB) = h2(v2, v3);
                    c[i][j][0] = 0.f; c[i][j][1] = 0.f;
                    c[i][j][2] = 0.f; c[i][j][3] = 0.f;
                }
            }
            __syncthreads();
        }
    }

    // ---------------- classifier + log_softmax ------------------------------
    {
        const float* bias = bmid + 7 * 256;
        float p[2][2][3];
#pragma unroll
        for (int i = 0; i < 2; i++)
#pragma unroll
            for (int h = 0; h < 2; h++)
                p[i][h][0] = p[i][h][1] = p[i][h][2] = 0.f;
#pragma unroll
        for (int i = 0; i < 2; i++) {
#pragma unroll
            for (int j = 0; j < 8; j++) {
                const int col = CB + 8 * j + 2 * (lane & 3);
                float2 bb = __ldg((const float2*)(bias + col));
                float v0 = c[i][j][0] + bb.x, v1 = c[i][j][1] + bb.y;
                float v2 = c[i][j][2] + bb.x, v3 = c[i][j][3] + bb.y;
                v0 = fmaxf(v0, 0.01f * v0); v1 = fmaxf(v1, 0.01f * v1);
                v2 = fmaxf(v2, 0.01f * v2); v3 = fmaxf(v3, 0.01f * v3);
                const float* w0 = Wlast + col * 3;
#pragma unroll
                for (int k = 0; k < 3; k++) {
                    float wa = __ldg(w0 + k), wb2 = __ldg(w0 + 3 + k);
                    p[i][0][k] = fmaf(v0, wa, fmaf(v1, wb2, p[i][0][k]));
                    p[i][1][k] = fmaf(v2, wa, fmaf(v3, wb2, p[i][1][k]));
                }
            }
        }
#pragma unroll
        for (int i = 0; i < 2; i++)
#pragma unroll
            for (int h = 0; h < 2; h++)
#pragma unroll
                for (int k = 0; k < 3; k++) {
                    float v = p[i][h][k];
                    v += __shfl_xor_sync(0xffffffffu, v, 1);
                    v += __shfl_xor_sync(0xffffffffu, v, 2);
                    p[i][h][k] = v;
                }
        float* pt = (float*)(smc + OFF_PT);   // overlay A plane: [128][4 ng][3]
        __syncthreads();                       // A-plane reads all done
        if ((lane & 3) == 0) {
#pragma unroll
            for (int i = 0; i < 2; i++)
#pragma unroll
                for (int h = 0; h < 2; h++) {
                    int row = RB + 16 * i + (lane >> 2) + 8 * h;
#pragma unroll
                    for (int k = 0; k < 3; k++)
                        pt[(row * 4 + ng) * 3 + k] = p[i][h][k];
                }
        }
    }
    __syncthreads();
    if (tid < 128) {
        const float* pt = (const float*)(smc + OFF_PT);
        float l[3];
#pragma unroll
        for (int k = 0; k < 3; k++) {
            float s = __ldg(blast + k);
#pragma unroll
            for (int g = 0; g < 4; g++) s += pt[(tid * 4 + g) * 3 + k];
            l[k] = s;
        }
        float mx  = fmaxf(l[0], fmaxf(l[1], l[2]));
        float lse = mx + logf(expf(l[0] - mx) + expf(l[1] - mx) + expf(l[2] - mx));
        float* o = out + (e0 + tid) * NOUT;
        o[0] = l[0] - lse; o[1] = l[1] - lse; o[2] = l[2] - lse;
    }
}

// ===========================================================================
extern "C" void kernel_launch(void* const* d_in, const int* in_sizes, int n_in,
                              void* d_out, int out_size)
{
    const float* x      = (const float*)d_in[0];
    const int*   ei_raw = (const int*)d_in[1];
    const float* eattr  = (const float*)d_in[2];
    const float* Wx     = (const float*)d_in[3];
    const float* bx     = (const float*)d_in[4];
    const float* W0     = (const float*)d_in[5];
    const float* b0     = (const float*)d_in[6];
    const float* Wmid   = (const float*)d_in[7];
    const float* bmid   = (const float*)d_in[8];
    const float* Wlast  = (const float*)d_in[9];
    const float* blast  = (const float*)d_in[10];
    float* out = (float*)d_out;

    const int N  = in_sizes[0] / DN;
    const int E  = in_sizes[2] / EA;
    const int n2 = 2 * E;
    const int nconv = (n2 + 255) / 256;

    cudaFuncSetAttribute(node_hmma_kernel,
                         cudaFuncAttributeMaxDynamicSharedMemorySize, SMEM_N);
    cudaFuncSetAttribute(uv_kernel,
                         cudaFuncAttributeMaxDynamicSharedMemorySize, SMEM_UV);
    cudaFuncSetAttribute(edge_hmma_kernel,
                         cudaFuncAttributeMaxDynamicSharedMemorySize, SMEM_E);

    prep_all<<<nconv + NPACK_BLK + NWX_BLK + NW0P_BLK, 256>>>(ei_raw, W0, Wmid, Wx, n2);
    node_hmma_kernel<<<N / 64, 128, SMEM_N>>>(x, bx);
    uv_kernel<<<N / 128, 256, SMEM_UV>>>();
    edge_hmma_kernel<<<E / 128, 512, SMEM_E>>>(eattr, b0, bmid, Wlast, blast,
                                               out, E);
}